// round 7
// baseline (speedup 1.0000x reference)
#include <cuda_runtime.h>
#include <math_constants.h>

// ChamferLoss bidirectional, single pass over the 16384x16384 d2 matrix.
// d2 = (|y|^2 - 2 x.y) + |x|^2 via packed fma.rn.f32x2 (2 gt cols per op).
// Thread owns 16 gt cols in regs; 2 pred rows interleaved per iteration
// (independent chains); col-min update shared across the row pair.

#define NPTS        16384
#define NROWG       256          // row groups (64 pred rows each)
#define NCOLG       4            // col groups (4096 gt cols each)
#define ROWS_PB     64
#define COLS_PT     16
#define THREADS     256

typedef unsigned long long ull;

__device__ float g_rowpartial[NCOLG * 8][NPTS];   // [colgroup*8+warp][row]
__device__ float g_colpartial[NROWG][NPTS];       // [rowgroup][col]  (16 MB)
__device__ float g_bsum[32];

union F2U { ull u; float2 f; };

__device__ __forceinline__ ull pack2(float a, float b) {
    ull r; asm("mov.b64 %0, {%1, %2};" : "=l"(r) : "f"(a), "f"(b)); return r;
}
__device__ __forceinline__ ull fma2(ull a, ull b, ull c) {
    ull d; asm("fma.rn.f32x2 %0, %1, %2, %3;" : "=l"(d) : "l"(a), "l"(b), "l"(c)); return d;
}
__device__ __forceinline__ ull add2(ull a, ull b) {
    ull d; asm("add.rn.f32x2 %0, %1, %2;" : "=l"(d) : "l"(a), "l"(b)); return d;
}

__global__ __launch_bounds__(THREADS, 2)
void chamfer_bidir_kernel(const float* __restrict__ pred,
                          const float* __restrict__ gt) {
    __shared__ float4 rowsm[ROWS_PB][2];   // {a0,a0,a1,a1},{a2,a2,x2,x2}

    int tid  = threadIdx.x;
    int lane = tid & 31;
    int wid  = tid >> 5;
    int rg   = blockIdx.x & (NROWG - 1);   // 0..255
    int cg   = blockIdx.x >> 8;            // 0..3
    int rowbase = rg * ROWS_PB;

    // ---- stage 64 pred rows into smem (duplicated for f32x2 broadcast) ----
    if (tid < ROWS_PB) {
        int r = rowbase + tid;
        float a0 = pred[3*r+0], a1 = pred[3*r+1], a2 = pred[3*r+2];
        float x2 = a0*a0 + a1*a1 + a2*a2;
        rowsm[tid][0] = make_float4(a0, a0, a1, a1);
        rowsm[tid][1] = make_float4(a2, a2, x2, x2);
    }

    // ---- 16 gt cols per thread, packed into registers ----
    ull B0[8], B1[8], B2[8], Y2[8];
    int cbase = cg * (THREADS * COLS_PT) + tid * COLS_PT;
    {
        float c[48];
        const float4* g4 = (const float4*)(gt + 3 * cbase);   // 192B aligned
        #pragma unroll
        for (int k = 0; k < 12; ++k) {
            float4 v = g4[k];
            c[4*k+0] = v.x; c[4*k+1] = v.y; c[4*k+2] = v.z; c[4*k+3] = v.w;
        }
        #pragma unroll
        for (int u = 0; u < 8; ++u) {
            float p0 = c[6*u+0], p1 = c[6*u+1], p2 = c[6*u+2];
            float q0 = c[6*u+3], q1 = c[6*u+4], q2 = c[6*u+5];
            B0[u] = pack2(-2.0f*p0, -2.0f*q0);
            B1[u] = pack2(-2.0f*p1, -2.0f*q1);
            B2[u] = pack2(-2.0f*p2, -2.0f*q2);
            Y2[u] = pack2(p0*p0 + p1*p1 + p2*p2, q0*q0 + q1*q1 + q2*q2);
        }
    }

    float cmin[COLS_PT];
    #pragma unroll
    for (int k = 0; k < COLS_PT; ++k) cmin[k] = CUDART_INF_F;

    __syncthreads();

    // ---- main loop: 32 groups of 2 interleaved rows ----
    for (int g = 0; g < ROWS_PB / 2; ++g) {
        const ulonglong2* rp0 = (const ulonglong2*)&rowsm[2*g + 0][0];
        const ulonglong2* rp1 = (const ulonglong2*)&rowsm[2*g + 1][0];
        ulonglong2 ra0 = rp0[0], rb0 = rp0[1];
        ulonglong2 ra1 = rp1[0], rb1 = rp1[1];
        ull A00 = ra0.x, A01 = ra0.y, A02 = rb0.x, X20 = rb0.y;
        ull A10 = ra1.x, A11 = ra1.y, A12 = rb1.x, X21 = rb1.y;

        float rm0 = CUDART_INF_F, rm1 = CUDART_INF_F;
        #pragma unroll
        for (int u = 0; u < 8; ++u) {
            F2U d0, d1;
            d0.u = add2(fma2(B0[u], A00, fma2(B1[u], A01, fma2(B2[u], A02, Y2[u]))), X20);
            d1.u = add2(fma2(B0[u], A10, fma2(B1[u], A11, fma2(B2[u], A12, Y2[u]))), X21);
            rm0 = fminf(rm0, fminf(d0.f.x, d0.f.y));
            rm1 = fminf(rm1, fminf(d1.f.x, d1.f.y));
            cmin[2*u+0] = fminf(cmin[2*u+0], fminf(d0.f.x, d1.f.x));
            cmin[2*u+1] = fminf(cmin[2*u+1], fminf(d0.f.y, d1.f.y));
        }
        // two interleaved shuffle-min trees (independent chains)
        #pragma unroll
        for (int o = 16; o; o >>= 1) {
            rm0 = fminf(rm0, __shfl_xor_sync(0xFFFFFFFFu, rm0, o));
            rm1 = fminf(rm1, __shfl_xor_sync(0xFFFFFFFFu, rm1, o));
        }
        if (lane == 0)
            *(float2*)&g_rowpartial[cg*8 + wid][rowbase + 2*g] = make_float2(rm0, rm1);
    }

    // ---- write col partials (vectorized, no conflicts across blocks) ----
    float4* cp4 = (float4*)&g_colpartial[rg][cbase];
    const float4* cm4 = (const float4*)cmin;
    #pragma unroll
    for (int k = 0; k < 4; ++k) cp4[k] = cm4[k];
}

__global__ __launch_bounds__(256)
void reduce1_kernel() {
    __shared__ float ssum[256];
    int bid = blockIdx.x;                 // 0..15 rows, 16..31 cols
    int tid = threadIdx.x;
    int idx = (bid & 15) * 1024 + tid * 4;

    float4 m = make_float4(CUDART_INF_F, CUDART_INF_F, CUDART_INF_F, CUDART_INF_F);
    if (bid < 16) {
        #pragma unroll
        for (int s = 0; s < NCOLG * 8; ++s) {
            float4 v = *(const float4*)&g_rowpartial[s][idx];
            m.x = fminf(m.x, v.x); m.y = fminf(m.y, v.y);
            m.z = fminf(m.z, v.z); m.w = fminf(m.w, v.w);
        }
    } else {
        #pragma unroll 8
        for (int s = 0; s < NROWG; ++s) {
            float4 v = *(const float4*)&g_colpartial[s][idx];
            m.x = fminf(m.x, v.x); m.y = fminf(m.y, v.y);
            m.z = fminf(m.z, v.z); m.w = fminf(m.w, v.w);
        }
    }
    float v = sqrtf(fmaxf(m.x, 0.0f)) + sqrtf(fmaxf(m.y, 0.0f))
            + sqrtf(fmaxf(m.z, 0.0f)) + sqrtf(fmaxf(m.w, 0.0f));

    ssum[tid] = v;
    __syncthreads();
    for (int s = 128; s > 0; s >>= 1) {
        if (tid < s) ssum[tid] += ssum[tid + s];
        __syncthreads();
    }
    if (tid == 0) g_bsum[bid] = ssum[0];
}

__global__ void reduce2_kernel(float* __restrict__ out) {
    float s = 0.0f;
    #pragma unroll
    for (int k = 0; k < 32; ++k) s += g_bsum[k];
    out[0] = s * (1.0f / 16384.0f);
}

extern "C" void kernel_launch(void* const* d_in, const int* in_sizes, int n_in,
                              void* d_out, int out_size) {
    const float* pred = (const float*)d_in[0];
    const float* gt   = (const float*)d_in[1];
    chamfer_bidir_kernel<<<NROWG * NCOLG, THREADS>>>(pred, gt);
    reduce1_kernel<<<32, 256>>>();
    reduce2_kernel<<<1, 1>>>((float*)d_out);
}

// round 8
// speedup vs baseline: 1.3387x; 1.3387x over previous
#include <cuda_runtime.h>
#include <math_constants.h>

// ChamferLoss bidirectional, single pass over the 16384x16384 d2 matrix.
// d2 = (|y|^2 - 2 x.y) + |x|^2 via packed fma.rn.f32x2 (2 gt cols per op).
// Thread owns 8 gt cols in regs (col-min accumulators in regs); pred rows
// broadcast from smem, 2 rows interleaved; row-min via single REDUX.MIN.S32
// (exact on positive floats). 3 blocks/SM (84 regs) for latency hiding.

#define NPTS        16384
#define NROWG       256          // row groups (64 pred rows each)
#define NCOLG       8            // col groups (2048 gt cols each)
#define ROWS_PB     64
#define COLS_PT     8
#define THREADS     256
#define NSLICE      (NCOLG * 8)  // 64 row-partial slices (per cg x warp)

typedef unsigned long long ull;

__device__ float g_rowpartial[NSLICE][NPTS];   // 4 MB
__device__ float g_colpartial[NROWG][NPTS];    // 16 MB
__device__ float g_bsum[80];

union F2U { ull u; float2 f; };

__device__ __forceinline__ ull pack2(float a, float b) {
    ull r; asm("mov.b64 %0, {%1, %2};" : "=l"(r) : "f"(a), "f"(b)); return r;
}
__device__ __forceinline__ ull fma2(ull a, ull b, ull c) {
    ull d; asm("fma.rn.f32x2 %0, %1, %2, %3;" : "=l"(d) : "l"(a), "l"(b), "l"(c)); return d;
}
__device__ __forceinline__ ull add2(ull a, ull b) {
    ull d; asm("add.rn.f32x2 %0, %1, %2;" : "=l"(d) : "l"(a), "l"(b)); return d;
}

__global__ __launch_bounds__(THREADS, 3)
void chamfer_bidir_kernel(const float* __restrict__ pred,
                          const float* __restrict__ gt) {
    __shared__ float4 rowsm[ROWS_PB][2];   // {a0,a0,a1,a1},{a2,a2,x2,x2}

    int tid  = threadIdx.x;
    int lane = tid & 31;
    int wid  = tid >> 5;
    int rg   = blockIdx.x & (NROWG - 1);   // 0..255
    int cg   = blockIdx.x >> 8;            // 0..7
    int rowbase = rg * ROWS_PB;

    // ---- stage 64 pred rows into smem (duplicated for f32x2 broadcast) ----
    if (tid < ROWS_PB) {
        int r = rowbase + tid;
        float a0 = pred[3*r+0], a1 = pred[3*r+1], a2 = pred[3*r+2];
        float x2 = a0*a0 + a1*a1 + a2*a2;
        rowsm[tid][0] = make_float4(a0, a0, a1, a1);
        rowsm[tid][1] = make_float4(a2, a2, x2, x2);
    }

    // ---- 8 gt cols per thread, packed into registers ----
    ull B0[4], B1[4], B2[4], Y2[4];
    int cbase = cg * (THREADS * COLS_PT) + tid * COLS_PT;
    {
        float c[24];
        const float4* g4 = (const float4*)(gt + 3 * cbase);   // 96B aligned
        #pragma unroll
        for (int k = 0; k < 6; ++k) {
            float4 v = g4[k];
            c[4*k+0] = v.x; c[4*k+1] = v.y; c[4*k+2] = v.z; c[4*k+3] = v.w;
        }
        #pragma unroll
        for (int u = 0; u < 4; ++u) {
            float p0 = c[6*u+0], p1 = c[6*u+1], p2 = c[6*u+2];
            float q0 = c[6*u+3], q1 = c[6*u+4], q2 = c[6*u+5];
            B0[u] = pack2(-2.0f*p0, -2.0f*q0);
            B1[u] = pack2(-2.0f*p1, -2.0f*q1);
            B2[u] = pack2(-2.0f*p2, -2.0f*q2);
            Y2[u] = pack2(p0*p0 + p1*p1 + p2*p2, q0*q0 + q1*q1 + q2*q2);
        }
    }

    float cmin[COLS_PT];
    #pragma unroll
    for (int k = 0; k < COLS_PT; ++k) cmin[k] = CUDART_INF_F;

    __syncthreads();

    float* rowout = &g_rowpartial[cg*8 + wid][rowbase];

    // ---- main loop: 32 groups of 2 interleaved rows ----
    #pragma unroll 4
    for (int g = 0; g < ROWS_PB / 2; ++g) {
        const ulonglong2* rp0 = (const ulonglong2*)&rowsm[2*g + 0][0];
        const ulonglong2* rp1 = (const ulonglong2*)&rowsm[2*g + 1][0];
        ulonglong2 ra0 = rp0[0], rb0 = rp0[1];
        ulonglong2 ra1 = rp1[0], rb1 = rp1[1];
        ull A00 = ra0.x, A01 = ra0.y, A02 = rb0.x, X20 = rb0.y;
        ull A10 = ra1.x, A11 = ra1.y, A12 = rb1.x, X21 = rb1.y;

        float rm0 = CUDART_INF_F, rm1 = CUDART_INF_F;
        #pragma unroll
        for (int u = 0; u < 4; ++u) {
            F2U d0, d1;
            d0.u = add2(fma2(B0[u], A00, fma2(B1[u], A01, fma2(B2[u], A02, Y2[u]))), X20);
            d1.u = add2(fma2(B0[u], A10, fma2(B1[u], A11, fma2(B2[u], A12, Y2[u]))), X21);
            rm0 = fminf(rm0, fminf(d0.f.x, d0.f.y));
            rm1 = fminf(rm1, fminf(d1.f.x, d1.f.y));
            cmin[2*u+0] = fminf(cmin[2*u+0], fminf(d0.f.x, d1.f.x));
            cmin[2*u+1] = fminf(cmin[2*u+1], fminf(d0.f.y, d1.f.y));
        }
        // Warp row-min: REDUX.MIN.S32 — exact for the positive d2 values here.
        int i0 = __reduce_min_sync(0xFFFFFFFFu, __float_as_int(rm0));
        int i1 = __reduce_min_sync(0xFFFFFFFFu, __float_as_int(rm1));
        if (lane == 0)
            *(float2*)(rowout + 2*g) = make_float2(__int_as_float(i0), __int_as_float(i1));
    }

    // ---- write col partials (vectorized; each thread owns distinct cols) ----
    float4* cp4 = (float4*)&g_colpartial[rg][cbase];
    const float4* cm4 = (const float4*)cmin;
    cp4[0] = cm4[0];
    cp4[1] = cm4[1];
}

__global__ __launch_bounds__(256)
void reduce1_kernel() {
    __shared__ float ssum[256];
    int bid = blockIdx.x;   // 0..15: row side (1024 rows each); 16..79: col side (256 cols each)
    int tid = threadIdx.x;
    float v;

    if (bid < 16) {
        int idx = bid * 1024 + tid * 4;
        float4 m = make_float4(CUDART_INF_F, CUDART_INF_F, CUDART_INF_F, CUDART_INF_F);
        #pragma unroll 8
        for (int s = 0; s < NSLICE; ++s) {
            float4 t = *(const float4*)&g_rowpartial[s][idx];
            m.x = fminf(m.x, t.x); m.y = fminf(m.y, t.y);
            m.z = fminf(m.z, t.z); m.w = fminf(m.w, t.w);
        }
        v = sqrtf(fmaxf(m.x, 0.0f)) + sqrtf(fmaxf(m.y, 0.0f))
          + sqrtf(fmaxf(m.z, 0.0f)) + sqrtf(fmaxf(m.w, 0.0f));
    } else {
        int col = (bid - 16) * 256 + tid;
        float m = CUDART_INF_F;
        #pragma unroll 8
        for (int s = 0; s < NROWG; ++s)
            m = fminf(m, g_colpartial[s][col]);
        v = sqrtf(fmaxf(m, 0.0f));
    }

    ssum[tid] = v;
    __syncthreads();
    for (int s = 128; s > 0; s >>= 1) {
        if (tid < s) ssum[tid] += ssum[tid + s];
        __syncthreads();
    }
    if (tid == 0) g_bsum[bid] = ssum[0];
}

__global__ void reduce2_kernel(float* __restrict__ out) {
    float s = 0.0f;
    #pragma unroll
    for (int k = 0; k < 80; ++k) s += g_bsum[k];
    out[0] = s * (1.0f / 16384.0f);
}

extern "C" void kernel_launch(void* const* d_in, const int* in_sizes, int n_in,
                              void* d_out, int out_size) {
    const float* pred = (const float*)d_in[0];
    const float* gt   = (const float*)d_in[1];
    chamfer_bidir_kernel<<<NROWG * NCOLG, THREADS>>>(pred, gt);
    reduce1_kernel<<<80, 256>>>();
    reduce2_kernel<<<1, 1>>>((float*)d_out);
}